// round 15
// baseline (speedup 1.0000x reference)
#include <cuda_runtime.h>
#include <cuda_bf16.h>
#include <mma.h>
#include <cstdint>
#include <cstddef>

#define BB 4
#define NN 4096
#define DD 256
#define RR 64
#define KK 16

// ---------------- device scratch (static; no runtime allocation) ----------------
__device__ __nv_bfloat16 g_scores[(size_t)BB * NN * NN];   // 128 MB approx scores (filter only)
__device__ float g_spf[(size_t)BB * NN * RR];
__device__ float g_dpf[(size_t)BB * NN * RR];
__device__ __nv_bfloat16 g_sph[(size_t)BB * NN * RR];
__device__ __nv_bfloat16 g_dph[(size_t)BB * NN * RR];
__device__ float g_w[(size_t)BB * NN * KK];
__device__ int   g_idx[(size_t)BB * NN * KK];
__device__ float g_kstate[NN];
__device__ float g_kval[(size_t)NN * DD];
__device__ float g_nk[(size_t)NN * DD];
__device__ float g_nv[(size_t)BB * NN * DD];
__device__ float g_nv2[(size_t)BB * NN * DD];
__device__ float g_nb[(size_t)BB * NN * DD];
__device__ float g_ds[(size_t)BB * NN];

// ---------------- reductions ----------------
__device__ __forceinline__ float warpSum(float v) {
#pragma unroll
    for (int o = 16; o > 0; o >>= 1) v += __shfl_xor_sync(0xffffffffu, v, o);
    return v;
}
__device__ __forceinline__ float warpMax(float v) {
#pragma unroll
    for (int o = 16; o > 0; o >>= 1) v = fmaxf(v, __shfl_xor_sync(0xffffffffu, v, o));
    return v;
}
__device__ __forceinline__ float blockSum256(float v) {
    __shared__ float sh[8];
    int wid = threadIdx.x >> 5, lid = threadIdx.x & 31;
    v = warpSum(v);
    if (lid == 0) sh[wid] = v;
    __syncthreads();
    float r = sh[0] + sh[1] + sh[2] + sh[3] + sh[4] + sh[5] + sh[6] + sh[7];
    __syncthreads();
    return r;
}
__device__ __forceinline__ float blockMax256(float v) {
    __shared__ float sh[8];
    int wid = threadIdx.x >> 5, lid = threadIdx.x & 31;
    v = warpMax(v);
    if (lid == 0) sh[wid] = v;
    __syncthreads();
    float r = fmaxf(fmaxf(fmaxf(sh[0], sh[1]), fmaxf(sh[2], sh[3])),
                    fmaxf(fmaxf(sh[4], sh[5]), fmaxf(sh[6], sh[7])));
    __syncthreads();
    return r;
}

// ---------------- layernorm over rows of 256 (optional chained second LN) ----------------
__global__ void __launch_bounds__(256) ln_kernel(const float* __restrict__ x, int srcMod,
                                                 const float* __restrict__ res,
                                                 const float* __restrict__ g,
                                                 const float* __restrict__ bt,
                                                 float* __restrict__ out,
                                                 const float* __restrict__ g2,
                                                 const float* __restrict__ bt2,
                                                 float* __restrict__ out2) {
    int row = blockIdx.x;
    int srow = srcMod ? (row & (srcMod - 1)) : row;
    int t = threadIdx.x;
    float v = x[(size_t)srow * DD + t];
    if (res) v += res[(size_t)row * DD + t];
    float mean = blockSum256(v) * (1.f / DD);
    float d = v - mean;
    float var = blockSum256(d * d) * (1.f / DD);
    float r1 = d * rsqrtf(var + 1e-5f) * g[t] + bt[t];
    out[(size_t)row * DD + t] = r1;
    if (g2) {
        float mean2 = blockSum256(r1) * (1.f / DD);
        float d2 = r1 - mean2;
        float var2 = blockSum256(d2 * d2) * (1.f / DD);
        out2[(size_t)row * DD + t] = d2 * rsqrtf(var2 + 1e-5f) * g2[t] + bt2[t];
    }
}

// ---------------- signed softmax over rows of 4096 ----------------
__global__ void __launch_bounds__(256) ss_kernel(const float* __restrict__ x, int xB,
                                                 const float* __restrict__ add,
                                                 float* __restrict__ out) {
    int b = blockIdx.x;
    const float* xr = x + (xB ? 0 : (size_t)b * NN);
    const float* ar = add ? add + (size_t)b * NN : nullptr;
    int t = threadIdx.x;
    float v[16];
    float mx = 0.f;
#pragma unroll
    for (int i = 0; i < 16; i++) {
        float u = xr[t + 256 * i];
        if (ar) u += ar[t + 256 * i];
        v[i] = u;
        mx = fmaxf(mx, fabsf(u));
    }
    mx = blockMax256(mx);
    float s = 0.f;
#pragma unroll
    for (int i = 0; i < 16; i++) s += expf(fabsf(v[i]) - mx);
    s = blockSum256(s);
    float inv = 1.f / s;
#pragma unroll
    for (int i = 0; i < 16; i++) {
        float u = v[i];
        float sg = (u > 0.f) ? 1.f : ((u < 0.f) ? -1.f : 0.f);
        out[(size_t)b * NN + t + 256 * i] = sg * expf(fabsf(u) - mx) * inv;
    }
}

// ---------------- projection: X[rows,256] @ W[256,64] -> fp32 + bf16(hi) ----------------
__global__ void __launch_bounds__(256) proj_kernel(const float* __restrict__ X,
                                                   const float* __restrict__ W,
                                                   float* __restrict__ outF,
                                                   __nv_bfloat16* __restrict__ outH,
                                                   int nrows) {
    int gi = blockIdx.x * 256 + threadIdx.x;
    int row = gi >> 4, cq = gi & 15;
    if (row >= nrows) return;
    const float4* W4 = (const float4*)W;
    const float4* X4 = (const float4*)(X + (size_t)row * DD);
    float4 acc = make_float4(0.f, 0.f, 0.f, 0.f);
#pragma unroll 8
    for (int d4 = 0; d4 < 64; d4++) {
        float4 xv = X4[d4];
        float4 w;
        w = W4[(d4 * 4 + 0) * 16 + cq];
        acc.x = fmaf(xv.x, w.x, acc.x); acc.y = fmaf(xv.x, w.y, acc.y);
        acc.z = fmaf(xv.x, w.z, acc.z); acc.w = fmaf(xv.x, w.w, acc.w);
        w = W4[(d4 * 4 + 1) * 16 + cq];
        acc.x = fmaf(xv.y, w.x, acc.x); acc.y = fmaf(xv.y, w.y, acc.y);
        acc.z = fmaf(xv.y, w.z, acc.z); acc.w = fmaf(xv.y, w.w, acc.w);
        w = W4[(d4 * 4 + 2) * 16 + cq];
        acc.x = fmaf(xv.z, w.x, acc.x); acc.y = fmaf(xv.z, w.y, acc.y);
        acc.z = fmaf(xv.z, w.z, acc.z); acc.w = fmaf(xv.z, w.w, acc.w);
        w = W4[(d4 * 4 + 3) * 16 + cq];
        acc.x = fmaf(xv.w, w.x, acc.x); acc.y = fmaf(xv.w, w.y, acc.y);
        acc.z = fmaf(xv.w, w.z, acc.z); acc.w = fmaf(xv.w, w.w, acc.w);
    }
    ((float4*)outF)[(size_t)row * 16 + cq] = acc;
    __nv_bfloat162 h0 = __nv_bfloat162(__float2bfloat16(acc.x), __float2bfloat16(acc.y));
    __nv_bfloat162 h1 = __nv_bfloat162(__float2bfloat16(acc.z), __float2bfloat16(acc.w));
    size_t base = (size_t)row * RR + cq * 4;
    __nv_bfloat162* oh = (__nv_bfloat162*)(outH + base);
    oh[0] = h0; oh[1] = h1;
}

// ---------------- dual projection: one X read, two weight matrices ----------------
__global__ void __launch_bounds__(256) proj_dual_kernel(const float* __restrict__ X,
                                                        const float* __restrict__ Wa,
                                                        const float* __restrict__ Wb,
                                                        float* __restrict__ outFa,
                                                        __nv_bfloat16* __restrict__ outHa,
                                                        float* __restrict__ outFb,
                                                        __nv_bfloat16* __restrict__ outHb,
                                                        int nrows) {
    int gi = blockIdx.x * 256 + threadIdx.x;
    int row = gi >> 4, cq = gi & 15;
    if (row >= nrows) return;
    const float4* Wa4 = (const float4*)Wa;
    const float4* Wb4 = (const float4*)Wb;
    const float4* X4 = (const float4*)(X + (size_t)row * DD);
    float4 aa = make_float4(0.f, 0.f, 0.f, 0.f);
    float4 ab = make_float4(0.f, 0.f, 0.f, 0.f);
#pragma unroll 4
    for (int d4 = 0; d4 < 64; d4++) {
        float4 xv = X4[d4];
        float xs[4] = {xv.x, xv.y, xv.z, xv.w};
#pragma unroll
        for (int u = 0; u < 4; u++) {
            float4 w = Wa4[(d4 * 4 + u) * 16 + cq];
            aa.x = fmaf(xs[u], w.x, aa.x); aa.y = fmaf(xs[u], w.y, aa.y);
            aa.z = fmaf(xs[u], w.z, aa.z); aa.w = fmaf(xs[u], w.w, aa.w);
            w = Wb4[(d4 * 4 + u) * 16 + cq];
            ab.x = fmaf(xs[u], w.x, ab.x); ab.y = fmaf(xs[u], w.y, ab.y);
            ab.z = fmaf(xs[u], w.z, ab.z); ab.w = fmaf(xs[u], w.w, ab.w);
        }
    }
    size_t base = (size_t)row * RR + cq * 4;
    ((float4*)outFa)[(size_t)row * 16 + cq] = aa;
    ((float4*)outFb)[(size_t)row * 16 + cq] = ab;
    __nv_bfloat162* oha = (__nv_bfloat162*)(outHa + base);
    oha[0] = __nv_bfloat162(__float2bfloat16(aa.x), __float2bfloat16(aa.y));
    oha[1] = __nv_bfloat162(__float2bfloat16(aa.z), __float2bfloat16(aa.w));
    __nv_bfloat162* ohb = (__nv_bfloat162*)(outHb + base);
    ohb[0] = __nv_bfloat162(__float2bfloat16(ab.x), __float2bfloat16(ab.y));
    ohb[1] = __nv_bfloat162(__float2bfloat16(ab.z), __float2bfloat16(ab.w));
}

// ---------------- WMMA approx score GEMM (hi-only), bf16 output ----------------
#define LDS_B 72
#define LDS_S 68

using namespace nvcuda;

__global__ void __launch_bounds__(256) wmma_score_kernel(const __nv_bfloat16* __restrict__ dph,
                                                         const __nv_bfloat16* __restrict__ sph,
                                                         __nv_bfloat16* __restrict__ out,
                                                         int dpB, int spB) {
    __shared__ __nv_bfloat16 sA[64 * LDS_B];
    __shared__ __nv_bfloat16 sB[128 * LDS_B];
    float* sStage = (float*)sB;

    int t = threadIdx.x;
    int w = t >> 5;
    int wn = w & 1;
    int wm = w >> 1;
    int n0 = blockIdx.x * 64;
    int b = blockIdx.y;
    const __nv_bfloat16* dphb = dph + (dpB ? 0 : (size_t)b * NN * RR);
    const __nv_bfloat16* sphb = sph + (spB ? 0 : (size_t)b * NN * RR);

#pragma unroll
    for (int i = 0; i < 2; i++) {
        int s = t + i * 256;
        int r = s >> 3, q = s & 7;
        *(float4*)&sA[r * LDS_B + q * 8] = *(const float4*)(dphb + (size_t)(n0 + r) * RR + q * 8);
    }

    for (int mt = 0; mt < 32; mt++) {
        int m0 = mt * 128;
        __syncthreads();
#pragma unroll
        for (int i = 0; i < 4; i++) {
            int s = t + i * 256;
            int r = s >> 3, q = s & 7;
            *(float4*)&sB[r * LDS_B + q * 8] = *(const float4*)(sphb + (size_t)(m0 + r) * RR + q * 8);
        }
        __syncthreads();

        wmma::fragment<wmma::accumulator, 16, 16, 16, float> acc[2][2];
#pragma unroll
        for (int i = 0; i < 2; i++)
#pragma unroll
            for (int j = 0; j < 2; j++) wmma::fill_fragment(acc[i][j], 0.f);

#pragma unroll
        for (int ks = 0; ks < 4; ks++) {
            wmma::fragment<wmma::matrix_a, 16, 16, 16, __nv_bfloat16, wmma::row_major> a0, a1;
            wmma::fragment<wmma::matrix_b, 16, 16, 16, __nv_bfloat16, wmma::col_major> b0, b1;
            wmma::load_matrix_sync(a0, &sA[(wn * 32 + 0) * LDS_B + ks * 16], LDS_B);
            wmma::load_matrix_sync(a1, &sA[(wn * 32 + 16) * LDS_B + ks * 16], LDS_B);
            wmma::load_matrix_sync(b0, &sB[(wm * 32 + 0) * LDS_B + ks * 16], LDS_B);
            wmma::load_matrix_sync(b1, &sB[(wm * 32 + 16) * LDS_B + ks * 16], LDS_B);
            wmma::mma_sync(acc[0][0], a0, b0, acc[0][0]);
            wmma::mma_sync(acc[0][1], a0, b1, acc[0][1]);
            wmma::mma_sync(acc[1][0], a1, b0, acc[1][0]);
            wmma::mma_sync(acc[1][1], a1, b1, acc[1][1]);
        }
#pragma unroll
        for (int i = 0; i < 2; i++)
#pragma unroll
            for (int j = 0; j < 2; j++)
#pragma unroll
                for (int e = 0; e < acc[i][j].num_elements; e++) acc[i][j].x[e] *= 0.125f;

#pragma unroll
        for (int h = 0; h < 2; h++) {
            __syncthreads();
            if ((wm >> 1) == h) {
                int cm = wm & 1;
#pragma unroll
                for (int i = 0; i < 2; i++)
#pragma unroll
                    for (int j = 0; j < 2; j++)
                        wmma::store_matrix_sync(&sStage[(wn * 32 + i * 16) * LDS_S + cm * 32 + j * 16],
                                                acc[i][j], LDS_S, wmma::mem_row_major);
            }
            __syncthreads();
#pragma unroll
            for (int p = 0; p < 2; p++) {
                int id = t + p * 256;
                int r = id >> 3;
                int cg = id & 7;
                const float* sp8 = &sStage[r * LDS_S + cg * 8];
                float4 v0 = *(const float4*)sp8;
                float4 v1 = *(const float4*)(sp8 + 4);
                __nv_bfloat162 o0 = __nv_bfloat162(__float2bfloat16(v0.x), __float2bfloat16(v0.y));
                __nv_bfloat162 o1 = __nv_bfloat162(__float2bfloat16(v0.z), __float2bfloat16(v0.w));
                __nv_bfloat162 o2 = __nv_bfloat162(__float2bfloat16(v1.x), __float2bfloat16(v1.y));
                __nv_bfloat162 o3 = __nv_bfloat162(__float2bfloat16(v1.z), __float2bfloat16(v1.w));
                uint4 pk;
                pk.x = *(unsigned int*)&o0; pk.y = *(unsigned int*)&o1;
                pk.z = *(unsigned int*)&o2; pk.w = *(unsigned int*)&o3;
                *(uint4*)(out + ((size_t)b * NN + n0 + r) * NN + m0 + h * 64 + cg * 8) = pk;
            }
        }
    }
}

// ---------------- top-16: bf16 approx filter (8% margin) + EXACT fp32 re-score ----------------
__device__ __forceinline__ float dot64(const float4* a4, const float* bp) {
    const float4* b4 = (const float4*)bp;
    float s = 0.f;
#pragma unroll
    for (int q = 0; q < 16; q++) {
        float4 a = a4[q], b = b4[q];
        s = fmaf(a.x, b.x, s); s = fmaf(a.y, b.y, s);
        s = fmaf(a.z, b.z, s); s = fmaf(a.w, b.w, s);
    }
    return s * 0.125f;
}

__global__ void __launch_bounds__(256) topk_kernel(const __nv_bfloat16* __restrict__ approx,
                                                   const float* __restrict__ dpf,
                                                   const float* __restrict__ spf,
                                                   int dpB, int spB,
                                                   float* __restrict__ wOut,
                                                   int* __restrict__ idxOut) {
    __shared__ float sEx[4096];
    __shared__ float sDp[64];
    __shared__ unsigned int sVal[256];
    __shared__ int sColA[256];
    __shared__ unsigned int warp2[8];
    __shared__ int sCnt;
    size_t row = blockIdx.x;
    int b = (int)(row >> 12);
    int n = (int)(row & (NN - 1));
    const __nv_bfloat16* sr = approx + row * (size_t)NN;
    const float* dpRow = dpf + (dpB ? 0 : (size_t)b * NN * RR) + (size_t)n * RR;
    const float* spb = spf + (spB ? 0 : (size_t)b * NN * RR);
    int t = threadIdx.x;
    int lid = t & 31, wid = t >> 5;

    if (t < 16) ((float4*)sDp)[t] = ((const float4*)dpRow)[t];

    unsigned int kk[16];
#pragma unroll
    for (int i = 0; i < 2; i++) {
        uint4 v = ((const uint4*)sr)[t + i * 256];
        unsigned int ws[4] = {v.x, v.y, v.z, v.w};
#pragma unroll
        for (int h = 0; h < 4; h++) {
            kk[i * 8 + h * 2 + 0] = (ws[h] << 16) & 0x7fffffffu;
            kk[i * 8 + h * 2 + 1] = ws[h] & 0x7fff0000u;
        }
    }

    unsigned int m1 = 0u, m2 = 0u;
#pragma unroll
    for (int e = 0; e < 16; e++) {
        unsigned int k = kk[e];
        if (k > m1) { m2 = m1; m1 = k; }
        else if (k > m2) { m2 = k; }
    }
#pragma unroll
    for (int o = 16; o > 0; o >>= 1) {
        unsigned int o1 = __shfl_xor_sync(0xffffffffu, m1, o);
        unsigned int o2 = __shfl_xor_sync(0xffffffffu, m2, o);
        if (o1 > m1) { m2 = (m1 > o2) ? m1 : o2; m1 = o1; }
        else { m2 = (m2 > o1) ? m2 : o1; }
    }
    if (lid == 0) warp2[wid] = m2;
    if (t == 0) sCnt = 0;
    __syncthreads();
    unsigned int T = warp2[0];
#pragma unroll
    for (int u = 1; u < 8; u++) T = (warp2[u] < T) ? warp2[u] : T;
    unsigned int Tm = __float_as_uint(__uint_as_float(T) * 0.92f);

#pragma unroll
    for (int e = 0; e < 16; e++) {
        if (kk[e] >= Tm) {
            int p = atomicAdd(&sCnt, 1);
            if (p < 256) sColA[p] = (t + (e >> 3) * 256) * 8 + (e & 7);
        }
    }
    __syncthreads();
    int C = sCnt;
    if (C <= 256) {
        if (t < C) {
            int ci = sColA[t];
            float ex = dot64((const float4*)sDp, spb + (size_t)ci * RR);
            sVal[t] = __float_as_uint(ex);
        }
        __syncthreads();
        if (t < C) {
            unsigned int vb = sVal[t];
            unsigned int ki = vb & 0x7fffffffu;
            int ci = sColA[t];
            int rank = 0;
            for (int j = 0; j < C; j++) {
                unsigned int kj = sVal[j] & 0x7fffffffu;
                int cj = sColA[j];
                rank += (kj > ki) || (kj == ki && cj < ci);
            }
            if (rank < KK) {
                wOut[row * KK + rank] = __uint_as_float(vb);
                idxOut[row * KK + rank] = ci;
            }
        }
    } else {
#pragma unroll
        for (int i = 0; i < 16; i++) {
            int c = t + i * 256;
            sEx[c] = dot64((const float4*)sDp, spb + (size_t)c * RR);
        }
        __syncthreads();
        if (t == 0) {
            unsigned int bk[16]; float bv[16]; int bc[16];
            int cnt = 0;
            for (int c = 0; c < NN; c++) {
                float val = sEx[c];
                unsigned int key = __float_as_uint(val) & 0x7fffffffu;
                if (cnt == 16 && key <= bk[15]) continue;
                int pos = (cnt < 16) ? cnt : 15;
                while (pos > 0 && bk[pos - 1] < key) {
                    bk[pos] = bk[pos - 1]; bv[pos] = bv[pos - 1]; bc[pos] = bc[pos - 1];
                    pos--;
                }
                bk[pos] = key; bv[pos] = val; bc[pos] = c;
                if (cnt < 16) cnt++;
            }
            for (int k = 0; k < KK; k++) {
                wOut[row * KK + k] = bv[k];
                idxOut[row * KK + k] = bc[k];
            }
        }
    }
}

// ---------------- fused message aggregation + residual LN + optional chained LN ----------------
__global__ void __launch_bounds__(256) msg_kernel(const float* __restrict__ w,
                                                  const int* __restrict__ idx,
                                                  const float* __restrict__ srcval, int srcB,
                                                  const float* __restrict__ state,
                                                  const float* __restrict__ res, int resMod,
                                                  const float* __restrict__ g,
                                                  const float* __restrict__ bt,
                                                  float* __restrict__ outVal,
                                                  float* __restrict__ dstate,
                                                  const float* __restrict__ g2,
                                                  const float* __restrict__ bt2,
                                                  float* __restrict__ outVal2) {
    __shared__ float sW[16];
    __shared__ int sI[16];
    __shared__ float sNorm[16];
    size_t row = blockIdx.x;
    int b = (int)(row >> 12);
    int t = threadIdx.x;
    if (t < 16) { sW[t] = w[row * KK + t]; sI[t] = idx[row * KK + t]; }
    __syncthreads();
    if (t == 0) {
        float mx = 0.f;
        for (int k = 0; k < 16; k++) mx = fmaxf(mx, fabsf(sW[k]));
        float e[16];
        float s = 0.f;
        for (int k = 0; k < 16; k++) { e[k] = expf(fabsf(sW[k]) - mx); s += e[k]; }
        float inv = 1.f / s;
        float dsum = 0.f;
        for (int k = 0; k < 16; k++) {
            float u = sW[k];
            float sg = (u > 0.f) ? 1.f : ((u < 0.f) ? -1.f : 0.f);
            float wt = sg * e[k] * inv;
            if (state) {
                float st = state[(size_t)b * NN + sI[k]];
                float sp = fmaxf(st, 0.f) + log1pf(expf(-fabsf(st)));  // softplus
                wt *= sp;
            }
            sW[k] = wt;
            dsum += wt;
        }
        dstate[row] = dsum;
    }
    __syncthreads();
    const float* base = srcval + (srcB ? 0 : (size_t)b * NN * DD);
    int wid = t >> 5, lid = t & 31;
    for (int k = wid; k < 16; k += 8) {
        const float* v = base + (size_t)sI[k] * DD;
        float ss = 0.f;
#pragma unroll
        for (int i = lid; i < 256; i += 32) { float x = v[i]; ss += x * x; }
        ss = warpSum(ss);
        if (lid == 0) sNorm[k] = sqrtf(ss) + 1e-6f;
    }
    __syncthreads();
    float acc = 0.f;
#pragma unroll
    for (int k = 0; k < 16; k++) {
        const float* v = base + (size_t)sI[k] * DD;
        acc = fmaf(sW[k] / sNorm[k], v[t], acc);
    }
    if (g) {
        int srow = resMod ? (int)(row & (resMod - 1)) : (int)row;
        float v = res[(size_t)srow * DD + t] + acc;
        float mean = blockSum256(v) * (1.f / DD);
        float d = v - mean;
        float var = blockSum256(d * d) * (1.f / DD);
        float r1 = d * rsqrtf(var + 1e-5f) * g[t] + bt[t];
        outVal[row * (size_t)DD + t] = r1;
        if (g2) {
            float mean2 = blockSum256(r1) * (1.f / DD);
            float d2 = r1 - mean2;
            float var2 = blockSum256(d2 * d2) * (1.f / DD);
            outVal2[row * (size_t)DD + t] = d2 * rsqrtf(var2 + 1e-5f) * g2[t] + bt2[t];
        }
    } else {
        outVal[row * (size_t)DD + t] = acc;
    }
}

// ---------------- host orchestration ----------------
extern "C" void kernel_launch(void* const* d_in, const int* in_sizes, int n_in,
                              void* d_out, int out_size) {
    const float* b_state    = (const float*)d_in[0];
    const float* b_val      = (const float*)d_in[1];
    const float* init_state = (const float*)d_in[2];
    const float* init_val   = (const float*)d_in[3];
    const float* U_bk = (const float*)d_in[4];
    const float* V_bk = (const float*)d_in[5];
    const float* U_kb = (const float*)d_in[6];
    const float* V_kb = (const float*)d_in[7];
    const float* U_p  = (const float*)d_in[8];
    const float* V_p  = (const float*)d_in[9];
    const float* kn_g = (const float*)d_in[10];
    const float* kn_b = (const float*)d_in[11];
    const float* bn_g = (const float*)d_in[12];
    const float* bn_b = (const float*)d_in[13];
    const float* pn_g = (const float*)d_in[14];
    const float* pn_b = (const float*)d_in[15];

    float* out = (float*)d_out;
    float* o_rstate = out;
    float* o_rval   = o_rstate + (size_t)BB * NN;
    float* o_pstate = o_rval + (size_t)BB * NN * DD;
    float* o_pval   = o_pstate + (size_t)BB * NN;
    float* o_bds    = o_pval + (size_t)BB * NN * DD;
    float* o_bdv    = o_bds + (size_t)BB * NN;

    float *p_spf, *p_dpf, *p_w, *p_kstate, *p_kval, *p_nk, *p_nv, *p_nv2, *p_nb, *p_ds;
    __nv_bfloat16 *p_scores, *p_sph, *p_dph;
    int* p_idx;
    cudaGetSymbolAddress((void**)&p_scores, g_scores);
    cudaGetSymbolAddress((void**)&p_spf, g_spf);
    cudaGetSymbolAddress((void**)&p_dpf, g_dpf);
    cudaGetSymbolAddress((void**)&p_sph, g_sph);
    cudaGetSymbolAddress((void**)&p_dph, g_dph);
    cudaGetSymbolAddress((void**)&p_w, g_w);
    cudaGetSymbolAddress((void**)&p_idx, g_idx);
    cudaGetSymbolAddress((void**)&p_kstate, g_kstate);
    cudaGetSymbolAddress((void**)&p_kval, g_kval);
    cudaGetSymbolAddress((void**)&p_nk, g_nk);
    cudaGetSymbolAddress((void**)&p_nv, g_nv);
    cudaGetSymbolAddress((void**)&p_nv2, g_nv2);
    cudaGetSymbolAddress((void**)&p_nb, g_nb);
    cudaGetSymbolAddress((void**)&p_ds, g_ds);

    dim3 mmaGrid(NN / 64, BB);

    // --- init: kval = LN(init_val, kn); nk = LN(kval, kn) fused ---
    ss_kernel<<<1, 256>>>(init_state, 1, nullptr, p_kstate);
    ln_kernel<<<NN, 256>>>(init_val, 0, nullptr, kn_g, kn_b, p_kval, kn_g, kn_b, p_nk);

    // --- transition 1: B -> K ---
    proj_kernel<<<(BB * NN * 16) / 256, 256>>>(b_val, U_bk, p_spf, p_sph, BB * NN);
    proj_kernel<<<(NN * 16) / 256, 256>>>(p_nk, V_bk, p_dpf, p_dph, NN);
    wmma_score_kernel<<<mmaGrid, 256>>>(p_dph, p_sph, p_scores, 1, 0);
    topk_kernel<<<BB * NN, 256>>>(p_scores, p_dpf, p_spf, 1, 0, p_w, p_idx);
    // o_rval = LN(kval + dv, kn); nv = LN(o_rval, pn) fused
    msg_kernel<<<BB * NN, 256>>>(p_w, p_idx, b_val, 0, b_state,
                                 p_kval, NN, kn_g, kn_b, o_rval, p_ds,
                                 pn_g, pn_b, p_nv);
    ss_kernel<<<BB, 256>>>(p_kstate, 1, p_ds, o_rstate);

    // --- propagation ---
    proj_dual_kernel<<<(BB * NN * 16) / 256, 256>>>(p_nv, U_p, V_p,
                                                    p_spf, p_sph, p_dpf, p_dph, BB * NN);
    wmma_score_kernel<<<mmaGrid, 256>>>(p_dph, p_sph, p_scores, 0, 0);
    topk_kernel<<<BB * NN, 256>>>(p_scores, p_dpf, p_spf, 0, 0, p_w, p_idx);
    // o_pval = LN(o_rval + dv, kn); nk2 = LN(o_pval, kn) fused (written to nv2)
    msg_kernel<<<BB * NN, 256>>>(p_w, p_idx, p_nv, 0, nullptr,
                                 o_rval, 0, kn_g, kn_b, o_pval, p_ds,
                                 kn_g, kn_b, p_nv2);
    ss_kernel<<<BB, 256>>>(o_rstate, 0, p_ds, o_pstate);

    // --- transition 2: K -> B (delta only) ---
    ln_kernel<<<BB * NN, 256>>>(b_val, 0, nullptr, bn_g, bn_b, p_nb,
                                nullptr, nullptr, nullptr);                 // nb
    proj_kernel<<<(BB * NN * 16) / 256, 256>>>(p_nv2, U_kb, p_spf, p_sph, BB * NN);
    proj_kernel<<<(BB * NN * 16) / 256, 256>>>(p_nb, V_kb, p_dpf, p_dph, BB * NN);
    wmma_score_kernel<<<mmaGrid, 256>>>(p_dph, p_sph, p_scores, 0, 0);
    topk_kernel<<<BB * NN, 256>>>(p_scores, p_dpf, p_spf, 0, 0, p_w, p_idx);
    msg_kernel<<<BB * NN, 256>>>(p_w, p_idx, p_nv2, 0, o_pstate,
                                 nullptr, 0, nullptr, nullptr, o_bdv, o_bds,
                                 nullptr, nullptr, nullptr);
}

// round 16
// speedup vs baseline: 1.0050x; 1.0050x over previous
#include <cuda_runtime.h>
#include <cuda_bf16.h>
#include <mma.h>
#include <cstdint>
#include <cstddef>

#define BB 4
#define NN 4096
#define DD 256
#define RR 64
#define KK 16

// ---------------- device scratch (static; no runtime allocation) ----------------
__device__ __nv_bfloat16 g_scores[(size_t)BB * NN * NN];   // 128 MB approx scores (filter only)
__device__ float g_spf[(size_t)BB * NN * RR];
__device__ float g_dpf[(size_t)BB * NN * RR];
__device__ __nv_bfloat16 g_sph[(size_t)BB * NN * RR];
__device__ __nv_bfloat16 g_dph[(size_t)BB * NN * RR];
__device__ float g_w[(size_t)BB * NN * KK];
__device__ int   g_idx[(size_t)BB * NN * KK];
__device__ float g_kstate[NN];
__device__ float g_kval[(size_t)NN * DD];
__device__ float g_nk[(size_t)NN * DD];
__device__ float g_nv[(size_t)BB * NN * DD];
__device__ float g_nv2[(size_t)BB * NN * DD];
__device__ float g_nb[(size_t)BB * NN * DD];
__device__ float g_ds[(size_t)BB * NN];

// ---------------- reductions ----------------
__device__ __forceinline__ float warpSum(float v) {
#pragma unroll
    for (int o = 16; o > 0; o >>= 1) v += __shfl_xor_sync(0xffffffffu, v, o);
    return v;
}
__device__ __forceinline__ float warpMax(float v) {
#pragma unroll
    for (int o = 16; o > 0; o >>= 1) v = fmaxf(v, __shfl_xor_sync(0xffffffffu, v, o));
    return v;
}
__device__ __forceinline__ float blockSum256(float v) {
    __shared__ float sh[8];
    int wid = threadIdx.x >> 5, lid = threadIdx.x & 31;
    v = warpSum(v);
    if (lid == 0) sh[wid] = v;
    __syncthreads();
    float r = sh[0] + sh[1] + sh[2] + sh[3] + sh[4] + sh[5] + sh[6] + sh[7];
    __syncthreads();
    return r;
}
__device__ __forceinline__ float blockMax256(float v) {
    __shared__ float sh[8];
    int wid = threadIdx.x >> 5, lid = threadIdx.x & 31;
    v = warpMax(v);
    if (lid == 0) sh[wid] = v;
    __syncthreads();
    float r = fmaxf(fmaxf(fmaxf(sh[0], sh[1]), fmaxf(sh[2], sh[3])),
                    fmaxf(fmaxf(sh[4], sh[5]), fmaxf(sh[6], sh[7])));
    __syncthreads();
    return r;
}

// ---------------- layernorm over rows of 256 (optional chained second LN) ----------------
__global__ void __launch_bounds__(256) ln_kernel(const float* __restrict__ x, int srcMod,
                                                 const float* __restrict__ res,
                                                 const float* __restrict__ g,
                                                 const float* __restrict__ bt,
                                                 float* __restrict__ out,
                                                 const float* __restrict__ g2,
                                                 const float* __restrict__ bt2,
                                                 float* __restrict__ out2) {
    int row = blockIdx.x;
    int srow = srcMod ? (row & (srcMod - 1)) : row;
    int t = threadIdx.x;
    float v = x[(size_t)srow * DD + t];
    if (res) v += res[(size_t)row * DD + t];
    float mean = blockSum256(v) * (1.f / DD);
    float d = v - mean;
    float var = blockSum256(d * d) * (1.f / DD);
    float r1 = d * rsqrtf(var + 1e-5f) * g[t] + bt[t];
    out[(size_t)row * DD + t] = r1;
    if (g2) {
        float mean2 = blockSum256(r1) * (1.f / DD);
        float d2 = r1 - mean2;
        float var2 = blockSum256(d2 * d2) * (1.f / DD);
        out2[(size_t)row * DD + t] = d2 * rsqrtf(var2 + 1e-5f) * g2[t] + bt2[t];
    }
}

// ---------------- signed softmax over rows of 4096 ----------------
__global__ void __launch_bounds__(256) ss_kernel(const float* __restrict__ x, int xB,
                                                 const float* __restrict__ add,
                                                 float* __restrict__ out) {
    int b = blockIdx.x;
    const float* xr = x + (xB ? 0 : (size_t)b * NN);
    const float* ar = add ? add + (size_t)b * NN : nullptr;
    int t = threadIdx.x;
    float v[16];
    float mx = 0.f;
#pragma unroll
    for (int i = 0; i < 16; i++) {
        float u = xr[t + 256 * i];
        if (ar) u += ar[t + 256 * i];
        v[i] = u;
        mx = fmaxf(mx, fabsf(u));
    }
    mx = blockMax256(mx);
    float s = 0.f;
#pragma unroll
    for (int i = 0; i < 16; i++) s += expf(fabsf(v[i]) - mx);
    s = blockSum256(s);
    float inv = 1.f / s;
#pragma unroll
    for (int i = 0; i < 16; i++) {
        float u = v[i];
        float sg = (u > 0.f) ? 1.f : ((u < 0.f) ? -1.f : 0.f);
        out[(size_t)b * NN + t + 256 * i] = sg * expf(fabsf(u) - mx) * inv;
    }
}

// ---------------- projection body: X[rows,256] @ W[256,64] -> fp32 + bf16(hi) ----------------
__device__ __forceinline__ void proj_body(const float* __restrict__ X,
                                          const float* __restrict__ W,
                                          float* __restrict__ outF,
                                          __nv_bfloat16* __restrict__ outH,
                                          int gi) {
    int row = gi >> 4, cq = gi & 15;
    const float4* W4 = (const float4*)W;
    const float4* X4 = (const float4*)(X + (size_t)row * DD);
    float4 acc = make_float4(0.f, 0.f, 0.f, 0.f);
#pragma unroll 8
    for (int d4 = 0; d4 < 64; d4++) {
        float4 xv = X4[d4];
        float4 w;
        w = W4[(d4 * 4 + 0) * 16 + cq];
        acc.x = fmaf(xv.x, w.x, acc.x); acc.y = fmaf(xv.x, w.y, acc.y);
        acc.z = fmaf(xv.x, w.z, acc.z); acc.w = fmaf(xv.x, w.w, acc.w);
        w = W4[(d4 * 4 + 1) * 16 + cq];
        acc.x = fmaf(xv.y, w.x, acc.x); acc.y = fmaf(xv.y, w.y, acc.y);
        acc.z = fmaf(xv.y, w.z, acc.z); acc.w = fmaf(xv.y, w.w, acc.w);
        w = W4[(d4 * 4 + 2) * 16 + cq];
        acc.x = fmaf(xv.z, w.x, acc.x); acc.y = fmaf(xv.z, w.y, acc.y);
        acc.z = fmaf(xv.z, w.z, acc.z); acc.w = fmaf(xv.z, w.w, acc.w);
        w = W4[(d4 * 4 + 3) * 16 + cq];
        acc.x = fmaf(xv.w, w.x, acc.x); acc.y = fmaf(xv.w, w.y, acc.y);
        acc.z = fmaf(xv.w, w.z, acc.z); acc.w = fmaf(xv.w, w.w, acc.w);
    }
    ((float4*)outF)[(size_t)row * 16 + cq] = acc;
    __nv_bfloat162 h0 = __nv_bfloat162(__float2bfloat16(acc.x), __float2bfloat16(acc.y));
    __nv_bfloat162 h1 = __nv_bfloat162(__float2bfloat16(acc.z), __float2bfloat16(acc.w));
    size_t base = (size_t)row * RR + cq * 4;
    __nv_bfloat162* oh = (__nv_bfloat162*)(outH + base);
    oh[0] = h0; oh[1] = h1;
}

// ---------------- two independent projection jobs co-scheduled in one grid ----------------
__global__ void __launch_bounds__(256) proj2_kernel(const float* __restrict__ Xa,
                                                    const float* __restrict__ Wa,
                                                    float* __restrict__ outFa,
                                                    __nv_bfloat16* __restrict__ outHa,
                                                    int blocksA,
                                                    const float* __restrict__ Xb,
                                                    const float* __restrict__ Wb,
                                                    float* __restrict__ outFb,
                                                    __nv_bfloat16* __restrict__ outHb) {
    int blk = blockIdx.x;
    if (blk < blocksA) {
        proj_body(Xa, Wa, outFa, outHa, blk * 256 + threadIdx.x);
    } else {
        proj_body(Xb, Wb, outFb, outHb, (blk - blocksA) * 256 + threadIdx.x);
    }
}

// ---------------- dual projection: one X read, two weight matrices ----------------
__global__ void __launch_bounds__(256) proj_dual_kernel(const float* __restrict__ X,
                                                        const float* __restrict__ Wa,
                                                        const float* __restrict__ Wb,
                                                        float* __restrict__ outFa,
                                                        __nv_bfloat16* __restrict__ outHa,
                                                        float* __restrict__ outFb,
                                                        __nv_bfloat16* __restrict__ outHb,
                                                        int nrows) {
    int gi = blockIdx.x * 256 + threadIdx.x;
    int row = gi >> 4, cq = gi & 15;
    if (row >= nrows) return;
    const float4* Wa4 = (const float4*)Wa;
    const float4* Wb4 = (const float4*)Wb;
    const float4* X4 = (const float4*)(X + (size_t)row * DD);
    float4 aa = make_float4(0.f, 0.f, 0.f, 0.f);
    float4 ab = make_float4(0.f, 0.f, 0.f, 0.f);
#pragma unroll 4
    for (int d4 = 0; d4 < 64; d4++) {
        float4 xv = X4[d4];
        float xs[4] = {xv.x, xv.y, xv.z, xv.w};
#pragma unroll
        for (int u = 0; u < 4; u++) {
            float4 w = Wa4[(d4 * 4 + u) * 16 + cq];
            aa.x = fmaf(xs[u], w.x, aa.x); aa.y = fmaf(xs[u], w.y, aa.y);
            aa.z = fmaf(xs[u], w.z, aa.z); aa.w = fmaf(xs[u], w.w, aa.w);
            w = Wb4[(d4 * 4 + u) * 16 + cq];
            ab.x = fmaf(xs[u], w.x, ab.x); ab.y = fmaf(xs[u], w.y, ab.y);
            ab.z = fmaf(xs[u], w.z, ab.z); ab.w = fmaf(xs[u], w.w, ab.w);
        }
    }
    size_t base = (size_t)row * RR + cq * 4;
    ((float4*)outFa)[(size_t)row * 16 + cq] = aa;
    ((float4*)outFb)[(size_t)row * 16 + cq] = ab;
    __nv_bfloat162* oha = (__nv_bfloat162*)(outHa + base);
    oha[0] = __nv_bfloat162(__float2bfloat16(aa.x), __float2bfloat16(aa.y));
    oha[1] = __nv_bfloat162(__float2bfloat16(aa.z), __float2bfloat16(aa.w));
    __nv_bfloat162* ohb = (__nv_bfloat162*)(outHb + base);
    ohb[0] = __nv_bfloat162(__float2bfloat16(ab.x), __float2bfloat16(ab.y));
    ohb[1] = __nv_bfloat162(__float2bfloat16(ab.z), __float2bfloat16(ab.w));
}

// ---------------- WMMA approx score GEMM (hi-only), bf16 output ----------------
#define LDS_B 72
#define LDS_S 68

using namespace nvcuda;

__global__ void __launch_bounds__(256) wmma_score_kernel(const __nv_bfloat16* __restrict__ dph,
                                                         const __nv_bfloat16* __restrict__ sph,
                                                         __nv_bfloat16* __restrict__ out,
                                                         int dpB, int spB) {
    __shared__ __nv_bfloat16 sA[64 * LDS_B];
    __shared__ __nv_bfloat16 sB[128 * LDS_B];
    float* sStage = (float*)sB;

    int t = threadIdx.x;
    int w = t >> 5;
    int wn = w & 1;
    int wm = w >> 1;
    int n0 = blockIdx.x * 64;
    int b = blockIdx.y;
    const __nv_bfloat16* dphb = dph + (dpB ? 0 : (size_t)b * NN * RR);
    const __nv_bfloat16* sphb = sph + (spB ? 0 : (size_t)b * NN * RR);

#pragma unroll
    for (int i = 0; i < 2; i++) {
        int s = t + i * 256;
        int r = s >> 3, q = s & 7;
        *(float4*)&sA[r * LDS_B + q * 8] = *(const float4*)(dphb + (size_t)(n0 + r) * RR + q * 8);
    }

    for (int mt = 0; mt < 32; mt++) {
        int m0 = mt * 128;
        __syncthreads();
#pragma unroll
        for (int i = 0; i < 4; i++) {
            int s = t + i * 256;
            int r = s >> 3, q = s & 7;
            *(float4*)&sB[r * LDS_B + q * 8] = *(const float4*)(sphb + (size_t)(m0 + r) * RR + q * 8);
        }
        __syncthreads();

        wmma::fragment<wmma::accumulator, 16, 16, 16, float> acc[2][2];
#pragma unroll
        for (int i = 0; i < 2; i++)
#pragma unroll
            for (int j = 0; j < 2; j++) wmma::fill_fragment(acc[i][j], 0.f);

#pragma unroll
        for (int ks = 0; ks < 4; ks++) {
            wmma::fragment<wmma::matrix_a, 16, 16, 16, __nv_bfloat16, wmma::row_major> a0, a1;
            wmma::fragment<wmma::matrix_b, 16, 16, 16, __nv_bfloat16, wmma::col_major> b0, b1;
            wmma::load_matrix_sync(a0, &sA[(wn * 32 + 0) * LDS_B + ks * 16], LDS_B);
            wmma::load_matrix_sync(a1, &sA[(wn * 32 + 16) * LDS_B + ks * 16], LDS_B);
            wmma::load_matrix_sync(b0, &sB[(wm * 32 + 0) * LDS_B + ks * 16], LDS_B);
            wmma::load_matrix_sync(b1, &sB[(wm * 32 + 16) * LDS_B + ks * 16], LDS_B);
            wmma::mma_sync(acc[0][0], a0, b0, acc[0][0]);
            wmma::mma_sync(acc[0][1], a0, b1, acc[0][1]);
            wmma::mma_sync(acc[1][0], a1, b0, acc[1][0]);
            wmma::mma_sync(acc[1][1], a1, b1, acc[1][1]);
        }
#pragma unroll
        for (int i = 0; i < 2; i++)
#pragma unroll
            for (int j = 0; j < 2; j++)
#pragma unroll
                for (int e = 0; e < acc[i][j].num_elements; e++) acc[i][j].x[e] *= 0.125f;

#pragma unroll
        for (int h = 0; h < 2; h++) {
            __syncthreads();
            if ((wm >> 1) == h) {
                int cm = wm & 1;
#pragma unroll
                for (int i = 0; i < 2; i++)
#pragma unroll
                    for (int j = 0; j < 2; j++)
                        wmma::store_matrix_sync(&sStage[(wn * 32 + i * 16) * LDS_S + cm * 32 + j * 16],
                                                acc[i][j], LDS_S, wmma::mem_row_major);
            }
            __syncthreads();
#pragma unroll
            for (int p = 0; p < 2; p++) {
                int id = t + p * 256;
                int r = id >> 3;
                int cg = id & 7;
                const float* sp8 = &sStage[r * LDS_S + cg * 8];
                float4 v0 = *(const float4*)sp8;
                float4 v1 = *(const float4*)(sp8 + 4);
                __nv_bfloat162 o0 = __nv_bfloat162(__float2bfloat16(v0.x), __float2bfloat16(v0.y));
                __nv_bfloat162 o1 = __nv_bfloat162(__float2bfloat16(v0.z), __float2bfloat16(v0.w));
                __nv_bfloat162 o2 = __nv_bfloat162(__float2bfloat16(v1.x), __float2bfloat16(v1.y));
                __nv_bfloat162 o3 = __nv_bfloat162(__float2bfloat16(v1.z), __float2bfloat16(v1.w));
                uint4 pk;
                pk.x = *(unsigned int*)&o0; pk.y = *(unsigned int*)&o1;
                pk.z = *(unsigned int*)&o2; pk.w = *(unsigned int*)&o3;
                *(uint4*)(out + ((size_t)b * NN + n0 + r) * NN + m0 + h * 64 + cg * 8) = pk;
            }
        }
    }
}

// ---------------- top-16: bf16 approx filter (8% margin) + EXACT fp32 re-score ----------------
__device__ __forceinline__ float dot64(const float4* a4, const float* bp) {
    const float4* b4 = (const float4*)bp;
    float s = 0.f;
#pragma unroll
    for (int q = 0; q < 16; q++) {
        float4 a = a4[q], b = b4[q];
        s = fmaf(a.x, b.x, s); s = fmaf(a.y, b.y, s);
        s = fmaf(a.z, b.z, s); s = fmaf(a.w, b.w, s);
    }
    return s * 0.125f;
}

__global__ void __launch_bounds__(256) topk_kernel(const __nv_bfloat16* __restrict__ approx,
                                                   const float* __restrict__ dpf,
                                                   const float* __restrict__ spf,
                                                   int dpB, int spB,
                                                   float* __restrict__ wOut,
                                                   int* __restrict__ idxOut) {
    __shared__ float sEx[4096];
    __shared__ float sDp[64];
    __shared__ unsigned int sVal[256];
    __shared__ int sColA[256];
    __shared__ unsigned int warp2[8];
    __shared__ int sCnt;
    size_t row = blockIdx.x;
    int b = (int)(row >> 12);
    int n = (int)(row & (NN - 1));
    const __nv_bfloat16* sr = approx + row * (size_t)NN;
    const float* dpRow = dpf + (dpB ? 0 : (size_t)b * NN * RR) + (size_t)n * RR;
    const float* spb = spf + (spB ? 0 : (size_t)b * NN * RR);
    int t = threadIdx.x;
    int lid = t & 31, wid = t >> 5;

    if (t < 16) ((float4*)sDp)[t] = ((const float4*)dpRow)[t];

    unsigned int kk[16];
#pragma unroll
    for (int i = 0; i < 2; i++) {
        uint4 v = ((const uint4*)sr)[t + i * 256];
        unsigned int ws[4] = {v.x, v.y, v.z, v.w};
#pragma unroll
        for (int h = 0; h < 4; h++) {
            kk[i * 8 + h * 2 + 0] = (ws[h] << 16) & 0x7fffffffu;
            kk[i * 8 + h * 2 + 1] = ws[h] & 0x7fff0000u;
        }
    }

    unsigned int m1 = 0u, m2 = 0u;
#pragma unroll
    for (int e = 0; e < 16; e++) {
        unsigned int k = kk[e];
        if (k > m1) { m2 = m1; m1 = k; }
        else if (k > m2) { m2 = k; }
    }
#pragma unroll
    for (int o = 16; o > 0; o >>= 1) {
        unsigned int o1 = __shfl_xor_sync(0xffffffffu, m1, o);
        unsigned int o2 = __shfl_xor_sync(0xffffffffu, m2, o);
        if (o1 > m1) { m2 = (m1 > o2) ? m1 : o2; m1 = o1; }
        else { m2 = (m2 > o1) ? m2 : o1; }
    }
    if (lid == 0) warp2[wid] = m2;
    if (t == 0) sCnt = 0;
    __syncthreads();
    unsigned int T = warp2[0];
#pragma unroll
    for (int u = 1; u < 8; u++) T = (warp2[u] < T) ? warp2[u] : T;
    unsigned int Tm = __float_as_uint(__uint_as_float(T) * 0.92f);

#pragma unroll
    for (int e = 0; e < 16; e++) {
        if (kk[e] >= Tm) {
            int p = atomicAdd(&sCnt, 1);
            if (p < 256) sColA[p] = (t + (e >> 3) * 256) * 8 + (e & 7);
        }
    }
    __syncthreads();
    int C = sCnt;
    if (C <= 256) {
        if (t < C) {
            int ci = sColA[t];
            float ex = dot64((const float4*)sDp, spb + (size_t)ci * RR);
            sVal[t] = __float_as_uint(ex);
        }
        __syncthreads();
        if (t < C) {
            unsigned int vb = sVal[t];
            unsigned int ki = vb & 0x7fffffffu;
            int ci = sColA[t];
            int rank = 0;
            for (int j = 0; j < C; j++) {
                unsigned int kj = sVal[j] & 0x7fffffffu;
                int cj = sColA[j];
                rank += (kj > ki) || (kj == ki && cj < ci);
            }
            if (rank < KK) {
                wOut[row * KK + rank] = __uint_as_float(vb);
                idxOut[row * KK + rank] = ci;
            }
        }
    } else {
#pragma unroll
        for (int i = 0; i < 16; i++) {
            int c = t + i * 256;
            sEx[c] = dot64((const float4*)sDp, spb + (size_t)c * RR);
        }
        __syncthreads();
        if (t == 0) {
            unsigned int bk[16]; float bv[16]; int bc[16];
            int cnt = 0;
            for (int c = 0; c < NN; c++) {
                float val = sEx[c];
                unsigned int key = __float_as_uint(val) & 0x7fffffffu;
                if (cnt == 16 && key <= bk[15]) continue;
                int pos = (cnt < 16) ? cnt : 15;
                while (pos > 0 && bk[pos - 1] < key) {
                    bk[pos] = bk[pos - 1]; bv[pos] = bv[pos - 1]; bc[pos] = bc[pos - 1];
                    pos--;
                }
                bk[pos] = key; bv[pos] = val; bc[pos] = c;
                if (cnt < 16) cnt++;
            }
            for (int k = 0; k < KK; k++) {
                wOut[row * KK + k] = bv[k];
                idxOut[row * KK + k] = bc[k];
            }
        }
    }
}

// ---------------- fused message aggregation + residual LN + optional chained LN ----------------
__global__ void __launch_bounds__(256) msg_kernel(const float* __restrict__ w,
                                                  const int* __restrict__ idx,
                                                  const float* __restrict__ srcval, int srcB,
                                                  const float* __restrict__ state,
                                                  const float* __restrict__ res, int resMod,
                                                  const float* __restrict__ g,
                                                  const float* __restrict__ bt,
                                                  float* __restrict__ outVal,
                                                  float* __restrict__ dstate,
                                                  const float* __restrict__ g2,
                                                  const float* __restrict__ bt2,
                                                  float* __restrict__ outVal2) {
    __shared__ float sW[16];
    __shared__ int sI[16];
    __shared__ float sNorm[16];
    size_t row = blockIdx.x;
    int b = (int)(row >> 12);
    int t = threadIdx.x;
    if (t < 16) { sW[t] = w[row * KK + t]; sI[t] = idx[row * KK + t]; }
    __syncthreads();
    if (t == 0) {
        float mx = 0.f;
        for (int k = 0; k < 16; k++) mx = fmaxf(mx, fabsf(sW[k]));
        float e[16];
        float s = 0.f;
        for (int k = 0; k < 16; k++) { e[k] = expf(fabsf(sW[k]) - mx); s += e[k]; }
        float inv = 1.f / s;
        float dsum = 0.f;
        for (int k = 0; k < 16; k++) {
            float u = sW[k];
            float sg = (u > 0.f) ? 1.f : ((u < 0.f) ? -1.f : 0.f);
            float wt = sg * e[k] * inv;
            if (state) {
                float st = state[(size_t)b * NN + sI[k]];
                float sp = fmaxf(st, 0.f) + log1pf(expf(-fabsf(st)));  // softplus
                wt *= sp;
            }
            sW[k] = wt;
            dsum += wt;
        }
        dstate[row] = dsum;
    }
    __syncthreads();
    const float* base = srcval + (srcB ? 0 : (size_t)b * NN * DD);
    int wid = t >> 5, lid = t & 31;
    for (int k = wid; k < 16; k += 8) {
        const float* v = base + (size_t)sI[k] * DD;
        float ss = 0.f;
#pragma unroll
        for (int i = lid; i < 256; i += 32) { float x = v[i]; ss += x * x; }
        ss = warpSum(ss);
        if (lid == 0) sNorm[k] = sqrtf(ss) + 1e-6f;
    }
    __syncthreads();
    float acc = 0.f;
#pragma unroll
    for (int k = 0; k < 16; k++) {
        const float* v = base + (size_t)sI[k] * DD;
        acc = fmaf(sW[k] / sNorm[k], v[t], acc);
    }
    if (g) {
        int srow = resMod ? (int)(row & (resMod - 1)) : (int)row;
        float v = res[(size_t)srow * DD + t] + acc;
        float mean = blockSum256(v) * (1.f / DD);
        float d = v - mean;
        float var = blockSum256(d * d) * (1.f / DD);
        float r1 = d * rsqrtf(var + 1e-5f) * g[t] + bt[t];
        outVal[row * (size_t)DD + t] = r1;
        if (g2) {
            float mean2 = blockSum256(r1) * (1.f / DD);
            float d2 = r1 - mean2;
            float var2 = blockSum256(d2 * d2) * (1.f / DD);
            outVal2[row * (size_t)DD + t] = d2 * rsqrtf(var2 + 1e-5f) * g2[t] + bt2[t];
        }
    } else {
        outVal[row * (size_t)DD + t] = acc;
    }
}

// ---------------- host orchestration ----------------
extern "C" void kernel_launch(void* const* d_in, const int* in_sizes, int n_in,
                              void* d_out, int out_size) {
    const float* b_state    = (const float*)d_in[0];
    const float* b_val      = (const float*)d_in[1];
    const float* init_state = (const float*)d_in[2];
    const float* init_val   = (const float*)d_in[3];
    const float* U_bk = (const float*)d_in[4];
    const float* V_bk = (const float*)d_in[5];
    const float* U_kb = (const float*)d_in[6];
    const float* V_kb = (const float*)d_in[7];
    const float* U_p  = (const float*)d_in[8];
    const float* V_p  = (const float*)d_in[9];
    const float* kn_g = (const float*)d_in[10];
    const float* kn_b = (const float*)d_in[11];
    const float* bn_g = (const float*)d_in[12];
    const float* bn_b = (const float*)d_in[13];
    const float* pn_g = (const float*)d_in[14];
    const float* pn_b = (const float*)d_in[15];

    float* out = (float*)d_out;
    float* o_rstate = out;
    float* o_rval   = o_rstate + (size_t)BB * NN;
    float* o_pstate = o_rval + (size_t)BB * NN * DD;
    float* o_pval   = o_pstate + (size_t)BB * NN;
    float* o_bds    = o_pval + (size_t)BB * NN * DD;
    float* o_bdv    = o_bds + (size_t)BB * NN;

    float *p_spf, *p_dpf, *p_w, *p_kstate, *p_kval, *p_nk, *p_nv, *p_nv2, *p_nb, *p_ds;
    __nv_bfloat16 *p_scores, *p_sph, *p_dph;
    int* p_idx;
    cudaGetSymbolAddress((void**)&p_scores, g_scores);
    cudaGetSymbolAddress((void**)&p_spf, g_spf);
    cudaGetSymbolAddress((void**)&p_dpf, g_dpf);
    cudaGetSymbolAddress((void**)&p_sph, g_sph);
    cudaGetSymbolAddress((void**)&p_dph, g_dph);
    cudaGetSymbolAddress((void**)&p_w, g_w);
    cudaGetSymbolAddress((void**)&p_idx, g_idx);
    cudaGetSymbolAddress((void**)&p_kstate, g_kstate);
    cudaGetSymbolAddress((void**)&p_kval, g_kval);
    cudaGetSymbolAddress((void**)&p_nk, g_nk);
    cudaGetSymbolAddress((void**)&p_nv, g_nv);
    cudaGetSymbolAddress((void**)&p_nv2, g_nv2);
    cudaGetSymbolAddress((void**)&p_nb, g_nb);
    cudaGetSymbolAddress((void**)&p_ds, g_ds);

    dim3 mmaGrid(NN / 64, BB);

    // --- init: kval = LN(init_val, kn); nk = LN(kval, kn) fused ---
    ss_kernel<<<1, 256>>>(init_state, 1, nullptr, p_kstate);
    ln_kernel<<<NN, 256>>>(init_val, 0, nullptr, kn_g, kn_b, p_kval, kn_g, kn_b, p_nk);

    // --- transition 1: B -> K ---
    // co-scheduled: sp = b_val@U_bk (1024 blocks) + dp = nk@V_bk (256 blocks)
    proj2_kernel<<<1024 + 256, 256>>>(b_val, U_bk, p_spf, p_sph, 1024,
                                      p_nk, V_bk, p_dpf, p_dph);
    wmma_score_kernel<<<mmaGrid, 256>>>(p_dph, p_sph, p_scores, 1, 0);
    topk_kernel<<<BB * NN, 256>>>(p_scores, p_dpf, p_spf, 1, 0, p_w, p_idx);
    msg_kernel<<<BB * NN, 256>>>(p_w, p_idx, b_val, 0, b_state,
                                 p_kval, NN, kn_g, kn_b, o_rval, p_ds,
                                 pn_g, pn_b, p_nv);
    ss_kernel<<<BB, 256>>>(p_kstate, 1, p_ds, o_rstate);

    // --- propagation ---
    proj_dual_kernel<<<(BB * NN * 16) / 256, 256>>>(p_nv, U_p, V_p,
                                                    p_spf, p_sph, p_dpf, p_dph, BB * NN);
    wmma_score_kernel<<<mmaGrid, 256>>>(p_dph, p_sph, p_scores, 0, 0);
    topk_kernel<<<BB * NN, 256>>>(p_scores, p_dpf, p_spf, 0, 0, p_w, p_idx);
    msg_kernel<<<BB * NN, 256>>>(p_w, p_idx, p_nv, 0, nullptr,
                                 o_rval, 0, kn_g, kn_b, o_pval, p_ds,
                                 kn_g, kn_b, p_nv2);
    ss_kernel<<<BB, 256>>>(o_rstate, 0, p_ds, o_pstate);

    // --- transition 2: K -> B (delta only) ---
    ln_kernel<<<BB * NN, 256>>>(b_val, 0, nullptr, bn_g, bn_b, p_nb,
                                nullptr, nullptr, nullptr);                 // nb
    // co-scheduled: sp = nv2@U_kb (1024 blocks) + dp = nb@V_kb (1024 blocks)
    proj2_kernel<<<2048, 256>>>(p_nv2, U_kb, p_spf, p_sph, 1024,
                                p_nb, V_kb, p_dpf, p_dph);
    wmma_score_kernel<<<mmaGrid, 256>>>(p_dph, p_sph, p_scores, 0, 0);
    topk_kernel<<<BB * NN, 256>>>(p_scores, p_dpf, p_spf, 0, 0, p_w, p_idx);
    msg_kernel<<<BB * NN, 256>>>(p_w, p_idx, p_nv2, 0, o_pstate,
                                 nullptr, 0, nullptr, nullptr, o_bdv, o_bds,
                                 nullptr, nullptr, nullptr);
}

// round 17
// speedup vs baseline: 1.0528x; 1.0475x over previous
#include <cuda_runtime.h>
#include <cuda_bf16.h>
#include <mma.h>
#include <cstdint>
#include <cstddef>

#define BB 4
#define NN 4096
#define DD 256
#define RR 64
#define KK 16

// ---------------- device scratch (static; no runtime allocation) ----------------
__device__ __nv_bfloat16 g_scores[(size_t)BB * NN * NN];   // 128 MB approx scores (filter only)
__device__ float g_spf[(size_t)BB * NN * RR];
__device__ float g_dpf[(size_t)BB * NN * RR];
__device__ __nv_bfloat16 g_sph[(size_t)BB * NN * RR];
__device__ __nv_bfloat16 g_dph[(size_t)BB * NN * RR];
__device__ float g_w[(size_t)BB * NN * KK];
__device__ int   g_idx[(size_t)BB * NN * KK];
__device__ float g_kstate[NN];
__device__ float g_kval[(size_t)NN * DD];
__device__ float g_nk[(size_t)NN * DD];
__device__ float g_nv[(size_t)BB * NN * DD];
__device__ float g_nv2[(size_t)BB * NN * DD];
__device__ float g_nb[(size_t)BB * NN * DD];
__device__ float g_ds[(size_t)BB * NN];

// ---------------- reductions ----------------
__device__ __forceinline__ float warpSum(float v) {
#pragma unroll
    for (int o = 16; o > 0; o >>= 1) v += __shfl_xor_sync(0xffffffffu, v, o);
    return v;
}
__device__ __forceinline__ float warpMax(float v) {
#pragma unroll
    for (int o = 16; o > 0; o >>= 1) v = fmaxf(v, __shfl_xor_sync(0xffffffffu, v, o));
    return v;
}
__device__ __forceinline__ float blockSum256(float v) {
    __shared__ float sh[8];
    int wid = threadIdx.x >> 5, lid = threadIdx.x & 31;
    v = warpSum(v);
    if (lid == 0) sh[wid] = v;
    __syncthreads();
    float r = sh[0] + sh[1] + sh[2] + sh[3] + sh[4] + sh[5] + sh[6] + sh[7];
    __syncthreads();
    return r;
}
__device__ __forceinline__ float blockMax256(float v) {
    __shared__ float sh[8];
    int wid = threadIdx.x >> 5, lid = threadIdx.x & 31;
    v = warpMax(v);
    if (lid == 0) sh[wid] = v;
    __syncthreads();
    float r = fmaxf(fmaxf(fmaxf(sh[0], sh[1]), fmaxf(sh[2], sh[3])),
                    fmaxf(fmaxf(sh[4], sh[5]), fmaxf(sh[6], sh[7])));
    __syncthreads();
    return r;
}

// ---------------- layernorm over rows of 256 (optional chained second LN) ----------------
__global__ void __launch_bounds__(256) ln_kernel(const float* __restrict__ x, int srcMod,
                                                 const float* __restrict__ res,
                                                 const float* __restrict__ g,
                                                 const float* __restrict__ bt,
                                                 float* __restrict__ out,
                                                 const float* __restrict__ g2,
                                                 const float* __restrict__ bt2,
                                                 float* __restrict__ out2) {
    int row = blockIdx.x;
    int srow = srcMod ? (row & (srcMod - 1)) : row;
    int t = threadIdx.x;
    float v = x[(size_t)srow * DD + t];
    if (res) v += res[(size_t)row * DD + t];
    float mean = blockSum256(v) * (1.f / DD);
    float d = v - mean;
    float var = blockSum256(d * d) * (1.f / DD);
    float r1 = d * rsqrtf(var + 1e-5f) * g[t] + bt[t];
    out[(size_t)row * DD + t] = r1;
    if (g2) {
        float mean2 = blockSum256(r1) * (1.f / DD);
        float d2 = r1 - mean2;
        float var2 = blockSum256(d2 * d2) * (1.f / DD);
        out2[(size_t)row * DD + t] = d2 * rsqrtf(var2 + 1e-5f) * g2[t] + bt2[t];
    }
}

// ---------------- signed softmax over rows of 4096 ----------------
__global__ void __launch_bounds__(256) ss_kernel(const float* __restrict__ x, int xB,
                                                 const float* __restrict__ add,
                                                 float* __restrict__ out) {
    int b = blockIdx.x;
    const float* xr = x + (xB ? 0 : (size_t)b * NN);
    const float* ar = add ? add + (size_t)b * NN : nullptr;
    int t = threadIdx.x;
    float v[16];
    float mx = 0.f;
#pragma unroll
    for (int i = 0; i < 16; i++) {
        float u = xr[t + 256 * i];
        if (ar) u += ar[t + 256 * i];
        v[i] = u;
        mx = fmaxf(mx, fabsf(u));
    }
    mx = blockMax256(mx);
    float s = 0.f;
#pragma unroll
    for (int i = 0; i < 16; i++) s += expf(fabsf(v[i]) - mx);
    s = blockSum256(s);
    float inv = 1.f / s;
#pragma unroll
    for (int i = 0; i < 16; i++) {
        float u = v[i];
        float sg = (u > 0.f) ? 1.f : ((u < 0.f) ? -1.f : 0.f);
        out[(size_t)b * NN + t + 256 * i] = sg * expf(fabsf(u) - mx) * inv;
    }
}

// ---------------- projection body: X[rows,256] @ W[256,64] -> fp32 + bf16(hi) ----------------
__device__ __forceinline__ void proj_body(const float* __restrict__ X,
                                          const float* __restrict__ W,
                                          float* __restrict__ outF,
                                          __nv_bfloat16* __restrict__ outH,
                                          int gi) {
    int row = gi >> 4, cq = gi & 15;
    const float4* W4 = (const float4*)W;
    const float4* X4 = (const float4*)(X + (size_t)row * DD);
    float4 acc = make_float4(0.f, 0.f, 0.f, 0.f);
#pragma unroll 8
    for (int d4 = 0; d4 < 64; d4++) {
        float4 xv = X4[d4];
        float4 w;
        w = W4[(d4 * 4 + 0) * 16 + cq];
        acc.x = fmaf(xv.x, w.x, acc.x); acc.y = fmaf(xv.x, w.y, acc.y);
        acc.z = fmaf(xv.x, w.z, acc.z); acc.w = fmaf(xv.x, w.w, acc.w);
        w = W4[(d4 * 4 + 1) * 16 + cq];
        acc.x = fmaf(xv.y, w.x, acc.x); acc.y = fmaf(xv.y, w.y, acc.y);
        acc.z = fmaf(xv.y, w.z, acc.z); acc.w = fmaf(xv.y, w.w, acc.w);
        w = W4[(d4 * 4 + 2) * 16 + cq];
        acc.x = fmaf(xv.z, w.x, acc.x); acc.y = fmaf(xv.z, w.y, acc.y);
        acc.z = fmaf(xv.z, w.z, acc.z); acc.w = fmaf(xv.z, w.w, acc.w);
        w = W4[(d4 * 4 + 3) * 16 + cq];
        acc.x = fmaf(xv.w, w.x, acc.x); acc.y = fmaf(xv.w, w.y, acc.y);
        acc.z = fmaf(xv.w, w.z, acc.z); acc.w = fmaf(xv.w, w.w, acc.w);
    }
    ((float4*)outF)[(size_t)row * 16 + cq] = acc;
    __nv_bfloat162 h0 = __nv_bfloat162(__float2bfloat16(acc.x), __float2bfloat16(acc.y));
    __nv_bfloat162 h1 = __nv_bfloat162(__float2bfloat16(acc.z), __float2bfloat16(acc.w));
    size_t base = (size_t)row * RR + cq * 4;
    __nv_bfloat162* oh = (__nv_bfloat162*)(outH + base);
    oh[0] = h0; oh[1] = h1;
}

// ---------------- two independent projection jobs co-scheduled in one grid ----------------
__global__ void __launch_bounds__(256) proj2_kernel(const float* __restrict__ Xa,
                                                    const float* __restrict__ Wa,
                                                    float* __restrict__ outFa,
                                                    __nv_bfloat16* __restrict__ outHa,
                                                    int blocksA,
                                                    const float* __restrict__ Xb,
                                                    const float* __restrict__ Wb,
                                                    float* __restrict__ outFb,
                                                    __nv_bfloat16* __restrict__ outHb) {
    int blk = blockIdx.x;
    if (blk < blocksA) {
        proj_body(Xa, Wa, outFa, outHa, blk * 256 + threadIdx.x);
    } else {
        proj_body(Xb, Wb, outFb, outHb, (blk - blocksA) * 256 + threadIdx.x);
    }
}

// ---------------- dual projection: one X read, two weight matrices ----------------
__global__ void __launch_bounds__(256) proj_dual_kernel(const float* __restrict__ X,
                                                        const float* __restrict__ Wa,
                                                        const float* __restrict__ Wb,
                                                        float* __restrict__ outFa,
                                                        __nv_bfloat16* __restrict__ outHa,
                                                        float* __restrict__ outFb,
                                                        __nv_bfloat16* __restrict__ outHb,
                                                        int nrows) {
    int gi = blockIdx.x * 256 + threadIdx.x;
    int row = gi >> 4, cq = gi & 15;
    if (row >= nrows) return;
    const float4* Wa4 = (const float4*)Wa;
    const float4* Wb4 = (const float4*)Wb;
    const float4* X4 = (const float4*)(X + (size_t)row * DD);
    float4 aa = make_float4(0.f, 0.f, 0.f, 0.f);
    float4 ab = make_float4(0.f, 0.f, 0.f, 0.f);
#pragma unroll 4
    for (int d4 = 0; d4 < 64; d4++) {
        float4 xv = X4[d4];
        float xs[4] = {xv.x, xv.y, xv.z, xv.w};
#pragma unroll
        for (int u = 0; u < 4; u++) {
            float4 w = Wa4[(d4 * 4 + u) * 16 + cq];
            aa.x = fmaf(xs[u], w.x, aa.x); aa.y = fmaf(xs[u], w.y, aa.y);
            aa.z = fmaf(xs[u], w.z, aa.z); aa.w = fmaf(xs[u], w.w, aa.w);
            w = Wb4[(d4 * 4 + u) * 16 + cq];
            ab.x = fmaf(xs[u], w.x, ab.x); ab.y = fmaf(xs[u], w.y, ab.y);
            ab.z = fmaf(xs[u], w.z, ab.z); ab.w = fmaf(xs[u], w.w, ab.w);
        }
    }
    size_t base = (size_t)row * RR + cq * 4;
    ((float4*)outFa)[(size_t)row * 16 + cq] = aa;
    ((float4*)outFb)[(size_t)row * 16 + cq] = ab;
    __nv_bfloat162* oha = (__nv_bfloat162*)(outHa + base);
    oha[0] = __nv_bfloat162(__float2bfloat16(aa.x), __float2bfloat16(aa.y));
    oha[1] = __nv_bfloat162(__float2bfloat16(aa.z), __float2bfloat16(aa.w));
    __nv_bfloat162* ohb = (__nv_bfloat162*)(outHb + base);
    ohb[0] = __nv_bfloat162(__float2bfloat16(ab.x), __float2bfloat16(ab.y));
    ohb[1] = __nv_bfloat162(__float2bfloat16(ab.z), __float2bfloat16(ab.w));
}

// ---------------- WMMA approx score GEMM (hi-only), bf16 output ----------------
// CTA tile 64(n) x 128(m), each CTA covers 8 m-tiles; grid (64, 4, 4) = 1024 CTAs.
#define LDS_B 72
#define LDS_S 68

using namespace nvcuda;

__global__ void __launch_bounds__(256) wmma_score_kernel(const __nv_bfloat16* __restrict__ dph,
                                                         const __nv_bfloat16* __restrict__ sph,
                                                         __nv_bfloat16* __restrict__ out,
                                                         int dpB, int spB) {
    __shared__ __nv_bfloat16 sA[64 * LDS_B];
    __shared__ __nv_bfloat16 sB[128 * LDS_B];
    float* sStage = (float*)sB;

    int t = threadIdx.x;
    int w = t >> 5;
    int wn = w & 1;
    int wm = w >> 1;
    int n0 = blockIdx.x * 64;
    int mc = blockIdx.y;            // m-chunk: 8 m-tiles of 128
    int b = blockIdx.z;
    const __nv_bfloat16* dphb = dph + (dpB ? 0 : (size_t)b * NN * RR);
    const __nv_bfloat16* sphb = sph + (spB ? 0 : (size_t)b * NN * RR);

#pragma unroll
    for (int i = 0; i < 2; i++) {
        int s = t + i * 256;
        int r = s >> 3, q = s & 7;
        *(float4*)&sA[r * LDS_B + q * 8] = *(const float4*)(dphb + (size_t)(n0 + r) * RR + q * 8);
    }

    for (int mt = mc * 8; mt < mc * 8 + 8; mt++) {
        int m0 = mt * 128;
        __syncthreads();
#pragma unroll
        for (int i = 0; i < 4; i++) {
            int s = t + i * 256;
            int r = s >> 3, q = s & 7;
            *(float4*)&sB[r * LDS_B + q * 8] = *(const float4*)(sphb + (size_t)(m0 + r) * RR + q * 8);
        }
        __syncthreads();

        wmma::fragment<wmma::accumulator, 16, 16, 16, float> acc[2][2];
#pragma unroll
        for (int i = 0; i < 2; i++)
#pragma unroll
            for (int j = 0; j < 2; j++) wmma::fill_fragment(acc[i][j], 0.f);

#pragma unroll
        for (int ks = 0; ks < 4; ks++) {
            wmma::fragment<wmma::matrix_a, 16, 16, 16, __nv_bfloat16, wmma::row_major> a0, a1;
            wmma::fragment<wmma::matrix_b, 16, 16, 16, __nv_bfloat16, wmma::col_major> b0, b1;
            wmma::load_matrix_sync(a0, &sA[(wn * 32 + 0) * LDS_B + ks * 16], LDS_B);
            wmma::load_matrix_sync(a1, &sA[(wn * 32 + 16) * LDS_B + ks * 16], LDS_B);
            wmma::load_matrix_sync(b0, &sB[(wm * 32 + 0) * LDS_B + ks * 16], LDS_B);
            wmma::load_matrix_sync(b1, &sB[(wm * 32 + 16) * LDS_B + ks * 16], LDS_B);
            wmma::mma_sync(acc[0][0], a0, b0, acc[0][0]);
            wmma::mma_sync(acc[0][1], a0, b1, acc[0][1]);
            wmma::mma_sync(acc[1][0], a1, b0, acc[1][0]);
            wmma::mma_sync(acc[1][1], a1, b1, acc[1][1]);
        }
#pragma unroll
        for (int i = 0; i < 2; i++)
#pragma unroll
            for (int j = 0; j < 2; j++)
#pragma unroll
                for (int e = 0; e < acc[i][j].num_elements; e++) acc[i][j].x[e] *= 0.125f;

#pragma unroll
        for (int h = 0; h < 2; h++) {
            __syncthreads();
            if ((wm >> 1) == h) {
                int cm = wm & 1;
#pragma unroll
                for (int i = 0; i < 2; i++)
#pragma unroll
                    for (int j = 0; j < 2; j++)
                        wmma::store_matrix_sync(&sStage[(wn * 32 + i * 16) * LDS_S + cm * 32 + j * 16],
                                                acc[i][j], LDS_S, wmma::mem_row_major);
            }
            __syncthreads();
#pragma unroll
            for (int p = 0; p < 2; p++) {
                int id = t + p * 256;
                int r = id >> 3;
                int cg = id & 7;
                const float* sp8 = &sStage[r * LDS_S + cg * 8];
                float4 v0 = *(const float4*)sp8;
                float4 v1 = *(const float4*)(sp8 + 4);
                __nv_bfloat162 o0 = __nv_bfloat162(__float2bfloat16(v0.x), __float2bfloat16(v0.y));
                __nv_bfloat162 o1 = __nv_bfloat162(__float2bfloat16(v0.z), __float2bfloat16(v0.w));
                __nv_bfloat162 o2 = __nv_bfloat162(__float2bfloat16(v1.x), __float2bfloat16(v1.y));
                __nv_bfloat162 o3 = __nv_bfloat162(__float2bfloat16(v1.z), __float2bfloat16(v1.w));
                uint4 pk;
                pk.x = *(unsigned int*)&o0; pk.y = *(unsigned int*)&o1;
                pk.z = *(unsigned int*)&o2; pk.w = *(unsigned int*)&o3;
                *(uint4*)(out + ((size_t)b * NN + n0 + r) * NN + m0 + h * 64 + cg * 8) = pk;
            }
        }
    }
}

// ---------------- top-16: bf16 approx filter (8% margin) + EXACT fp32 re-score ----------------
__device__ __forceinline__ float dot64(const float4* a4, const float* bp) {
    const float4* b4 = (const float4*)bp;
    float s = 0.f;
#pragma unroll
    for (int q = 0; q < 16; q++) {
        float4 a = a4[q], b = b4[q];
        s = fmaf(a.x, b.x, s); s = fmaf(a.y, b.y, s);
        s = fmaf(a.z, b.z, s); s = fmaf(a.w, b.w, s);
    }
    return s * 0.125f;
}

__global__ void __launch_bounds__(256) topk_kernel(const __nv_bfloat16* __restrict__ approx,
                                                   const float* __restrict__ dpf,
                                                   const float* __restrict__ spf,
                                                   int dpB, int spB,
                                                   float* __restrict__ wOut,
                                                   int* __restrict__ idxOut) {
    __shared__ float sEx[4096];
    __shared__ float sDp[64];
    __shared__ unsigned int sVal[256];
    __shared__ int sColA[256];
    __shared__ unsigned int warp2[8];
    __shared__ int sCnt;
    size_t row = blockIdx.x;
    int b = (int)(row >> 12);
    int n = (int)(row & (NN - 1));
    const __nv_bfloat16* sr = approx + row * (size_t)NN;
    const float* dpRow = dpf + (dpB ? 0 : (size_t)b * NN * RR) + (size_t)n * RR;
    const float* spb = spf + (spB ? 0 : (size_t)b * NN * RR);
    int t = threadIdx.x;
    int lid = t & 31, wid = t >> 5;

    if (t < 16) ((float4*)sDp)[t] = ((const float4*)dpRow)[t];

    unsigned int kk[16];
#pragma unroll
    for (int i = 0; i < 2; i++) {
        uint4 v = ((const uint4*)sr)[t + i * 256];
        unsigned int ws[4] = {v.x, v.y, v.z, v.w};
#pragma unroll
        for (int h = 0; h < 4; h++) {
            kk[i * 8 + h * 2 + 0] = (ws[h] << 16) & 0x7fffffffu;
            kk[i * 8 + h * 2 + 1] = ws[h] & 0x7fff0000u;
        }
    }

    unsigned int m1 = 0u, m2 = 0u;
#pragma unroll
    for (int e = 0; e < 16; e++) {
        unsigned int k = kk[e];
        if (k > m1) { m2 = m1; m1 = k; }
        else if (k > m2) { m2 = k; }
    }
#pragma unroll
    for (int o = 16; o > 0; o >>= 1) {
        unsigned int o1 = __shfl_xor_sync(0xffffffffu, m1, o);
        unsigned int o2 = __shfl_xor_sync(0xffffffffu, m2, o);
        if (o1 > m1) { m2 = (m1 > o2) ? m1 : o2; m1 = o1; }
        else { m2 = (m2 > o1) ? m2 : o1; }
    }
    if (lid == 0) warp2[wid] = m2;
    if (t == 0) sCnt = 0;
    __syncthreads();
    unsigned int T = warp2[0];
#pragma unroll
    for (int u = 1; u < 8; u++) T = (warp2[u] < T) ? warp2[u] : T;
    unsigned int Tm = __float_as_uint(__uint_as_float(T) * 0.92f);

#pragma unroll
    for (int e = 0; e < 16; e++) {
        if (kk[e] >= Tm) {
            int p = atomicAdd(&sCnt, 1);
            if (p < 256) sColA[p] = (t + (e >> 3) * 256) * 8 + (e & 7);
        }
    }
    __syncthreads();
    int C = sCnt;
    if (C <= 256) {
        if (t < C) {
            int ci = sColA[t];
            float ex = dot64((const float4*)sDp, spb + (size_t)ci * RR);
            sVal[t] = __float_as_uint(ex);
        }
        __syncthreads();
        if (t < C) {
            unsigned int vb = sVal[t];
            unsigned int ki = vb & 0x7fffffffu;
            int ci = sColA[t];
            int rank = 0;
            for (int j = 0; j < C; j++) {
                unsigned int kj = sVal[j] & 0x7fffffffu;
                int cj = sColA[j];
                rank += (kj > ki) || (kj == ki && cj < ci);
            }
            if (rank < KK) {
                wOut[row * KK + rank] = __uint_as_float(vb);
                idxOut[row * KK + rank] = ci;
            }
        }
    } else {
#pragma unroll
        for (int i = 0; i < 16; i++) {
            int c = t + i * 256;
            sEx[c] = dot64((const float4*)sDp, spb + (size_t)c * RR);
        }
        __syncthreads();
        if (t == 0) {
            unsigned int bk[16]; float bv[16]; int bc[16];
            int cnt = 0;
            for (int c = 0; c < NN; c++) {
                float val = sEx[c];
                unsigned int key = __float_as_uint(val) & 0x7fffffffu;
                if (cnt == 16 && key <= bk[15]) continue;
                int pos = (cnt < 16) ? cnt : 15;
                while (pos > 0 && bk[pos - 1] < key) {
                    bk[pos] = bk[pos - 1]; bv[pos] = bv[pos - 1]; bc[pos] = bc[pos - 1];
                    pos--;
                }
                bk[pos] = key; bv[pos] = val; bc[pos] = c;
                if (cnt < 16) cnt++;
            }
            for (int k = 0; k < KK; k++) {
                wOut[row * KK + k] = bv[k];
                idxOut[row * KK + k] = bc[k];
            }
        }
    }
}

// ---------------- fused message aggregation + residual LN + optional chained LN ----------------
__global__ void __launch_bounds__(256) msg_kernel(const float* __restrict__ w,
                                                  const int* __restrict__ idx,
                                                  const float* __restrict__ srcval, int srcB,
                                                  const float* __restrict__ state,
                                                  const float* __restrict__ res, int resMod,
                                                  const float* __restrict__ g,
                                                  const float* __restrict__ bt,
                                                  float* __restrict__ outVal,
                                                  float* __restrict__ dstate,
                                                  const float* __restrict__ g2,
                                                  const float* __restrict__ bt2,
                                                  float* __restrict__ outVal2) {
    __shared__ float sW[16];
    __shared__ int sI[16];
    __shared__ float sNorm[16];
    size_t row = blockIdx.x;
    int b = (int)(row >> 12);
    int t = threadIdx.x;
    if (t < 16) { sW[t] = w[row * KK + t]; sI[t] = idx[row * KK + t]; }
    __syncthreads();
    if (t == 0) {
        float mx = 0.f;
        for (int k = 0; k < 16; k++) mx = fmaxf(mx, fabsf(sW[k]));
        float e[16];
        float s = 0.f;
        for (int k = 0; k < 16; k++) { e[k] = expf(fabsf(sW[k]) - mx); s += e[k]; }
        float inv = 1.f / s;
        float dsum = 0.f;
        for (int k = 0; k < 16; k++) {
            float u = sW[k];
            float sg = (u > 0.f) ? 1.f : ((u < 0.f) ? -1.f : 0.f);
            float wt = sg * e[k] * inv;
            if (state) {
                float st = state[(size_t)b * NN + sI[k]];
                float sp = fmaxf(st, 0.f) + log1pf(expf(-fabsf(st)));  // softplus
                wt *= sp;
            }
            sW[k] = wt;
            dsum += wt;
        }
        dstate[row] = dsum;
    }
    __syncthreads();
    const float* base = srcval + (srcB ? 0 : (size_t)b * NN * DD);
    int wid = t >> 5, lid = t & 31;
    for (int k = wid; k < 16; k += 8) {
        const float* v = base + (size_t)sI[k] * DD;
        float ss = 0.f;
#pragma unroll
        for (int i = lid; i < 256; i += 32) { float x = v[i]; ss += x * x; }
        ss = warpSum(ss);
        if (lid == 0) sNorm[k] = sqrtf(ss) + 1e-6f;
    }
    __syncthreads();
    float acc = 0.f;
#pragma unroll
    for (int k = 0; k < 16; k++) {
        const float* v = base + (size_t)sI[k] * DD;
        acc = fmaf(sW[k] / sNorm[k], v[t], acc);
    }
    if (g) {
        int srow = resMod ? (int)(row & (resMod - 1)) : (int)row;
        float v = res[(size_t)srow * DD + t] + acc;
        float mean = blockSum256(v) * (1.f / DD);
        float d = v - mean;
        float var = blockSum256(d * d) * (1.f / DD);
        float r1 = d * rsqrtf(var + 1e-5f) * g[t] + bt[t];
        outVal[row * (size_t)DD + t] = r1;
        if (g2) {
            float mean2 = blockSum256(r1) * (1.f / DD);
            float d2 = r1 - mean2;
            float var2 = blockSum256(d2 * d2) * (1.f / DD);
            outVal2[row * (size_t)DD + t] = d2 * rsqrtf(var2 + 1e-5f) * g2[t] + bt2[t];
        }
    } else {
        outVal[row * (size_t)DD + t] = acc;
    }
}

// ---------------- host orchestration ----------------
extern "C" void kernel_launch(void* const* d_in, const int* in_sizes, int n_in,
                              void* d_out, int out_size) {
    const float* b_state    = (const float*)d_in[0];
    const float* b_val      = (const float*)d_in[1];
    const float* init_state = (const float*)d_in[2];
    const float* init_val   = (const float*)d_in[3];
    const float* U_bk = (const float*)d_in[4];
    const float* V_bk = (const float*)d_in[5];
    const float* U_kb = (const float*)d_in[6];
    const float* V_kb = (const float*)d_in[7];
    const float* U_p  = (const float*)d_in[8];
    const float* V_p  = (const float*)d_in[9];
    const float* kn_g = (const float*)d_in[10];
    const float* kn_b = (const float*)d_in[11];
    const float* bn_g = (const float*)d_in[12];
    const float* bn_b = (const float*)d_in[13];
    const float* pn_g = (const float*)d_in[14];
    const float* pn_b = (const float*)d_in[15];

    float* out = (float*)d_out;
    float* o_rstate = out;
    float* o_rval   = o_rstate + (size_t)BB * NN;
    float* o_pstate = o_rval + (size_t)BB * NN * DD;
    float* o_pval   = o_pstate + (size_t)BB * NN;
    float* o_bds    = o_pval + (size_t)BB * NN * DD;
    float* o_bdv    = o_bds + (size_t)BB * NN;

    float *p_spf, *p_dpf, *p_w, *p_kstate, *p_kval, *p_nk, *p_nv, *p_nv2, *p_nb, *p_ds;
    __nv_bfloat16 *p_scores, *p_sph, *p_dph;
    int* p_idx;
    cudaGetSymbolAddress((void**)&p_scores, g_scores);
    cudaGetSymbolAddress((void**)&p_spf, g_spf);
    cudaGetSymbolAddress((void**)&p_dpf, g_dpf);
    cudaGetSymbolAddress((void**)&p_sph, g_sph);
    cudaGetSymbolAddress((void**)&p_dph, g_dph);
    cudaGetSymbolAddress((void**)&p_w, g_w);
    cudaGetSymbolAddress((void**)&p_idx, g_idx);
    cudaGetSymbolAddress((void**)&p_kstate, g_kstate);
    cudaGetSymbolAddress((void**)&p_kval, g_kval);
    cudaGetSymbolAddress((void**)&p_nk, g_nk);
    cudaGetSymbolAddress((void**)&p_nv, g_nv);
    cudaGetSymbolAddress((void**)&p_nv2, g_nv2);
    cudaGetSymbolAddress((void**)&p_nb, g_nb);
    cudaGetSymbolAddress((void**)&p_ds, g_ds);

    dim3 mmaGrid(NN / 64, 4, BB);   // 1024 CTAs: n-tile x m-chunk x batch

    // --- init: kval = LN(init_val, kn); nk = LN(kval, kn) fused ---
    ss_kernel<<<1, 256>>>(init_state, 1, nullptr, p_kstate);
    ln_kernel<<<NN, 256>>>(init_val, 0, nullptr, kn_g, kn_b, p_kval, kn_g, kn_b, p_nk);

    // --- transition 1: B -> K ---
    proj2_kernel<<<1024 + 256, 256>>>(b_val, U_bk, p_spf, p_sph, 1024,
                                      p_nk, V_bk, p_dpf, p_dph);
    wmma_score_kernel<<<mmaGrid, 256>>>(p_dph, p_sph, p_scores, 1, 0);
    topk_kernel<<<BB * NN, 256>>>(p_scores, p_dpf, p_spf, 1, 0, p_w, p_idx);
    msg_kernel<<<BB * NN, 256>>>(p_w, p_idx, b_val, 0, b_state,
                                 p_kval, NN, kn_g, kn_b, o_rval, p_ds,
                                 pn_g, pn_b, p_nv);
    ss_kernel<<<BB, 256>>>(p_kstate, 1, p_ds, o_rstate);

    // --- propagation ---
    proj_dual_kernel<<<(BB * NN * 16) / 256, 256>>>(p_nv, U_p, V_p,
                                                    p_spf, p_sph, p_dpf, p_dph, BB * NN);
    wmma_score_kernel<<<mmaGrid, 256>>>(p_dph, p_sph, p_scores, 0, 0);
    topk_kernel<<<BB * NN, 256>>>(p_scores, p_dpf, p_spf, 0, 0, p_w, p_idx);
    msg_kernel<<<BB * NN, 256>>>(p_w, p_idx, p_nv, 0, nullptr,
                                 o_rval, 0, kn_g, kn_b, o_pval, p_ds,
                                 kn_g, kn_b, p_nv2);
    ss_kernel<<<BB, 256>>>(o_rstate, 0, p_ds, o_pstate);

    // --- transition 2: K -> B (delta only) ---
    ln_kernel<<<BB * NN, 256>>>(b_val, 0, nullptr, bn_g, bn_b, p_nb,
                                nullptr, nullptr, nullptr);                 // nb
    proj2_kernel<<<2048, 256>>>(p_nv2, U_kb, p_spf, p_sph, 1024,
                                p_nb, V_kb, p_dpf, p_dph);
    wmma_score_kernel<<<mmaGrid, 256>>>(p_dph, p_sph, p_scores, 0, 0);
    topk_kernel<<<BB * NN, 256>>>(p_scores, p_dpf, p_spf, 0, 0, p_w, p_idx);
    msg_kernel<<<BB * NN, 256>>>(p_w, p_idx, p_nv2, 0, o_pstate,
                                 nullptr, 0, nullptr, nullptr, o_bdv, o_bds,
                                 nullptr, nullptr, nullptr);
}